// round 13
// baseline (speedup 1.0000x reference)
#include <cuda_runtime.h>
#include <math_constants.h>

// Problem constants (fixed by reference setup_inputs)
#define B_   8
#define C_   24
#define H_   320
#define W_   640
#define HW_  (H_ * W_)          // 204800
#define NPIX (B_ * HW_)         // 1638400
#define NU_  (NPIX / 4)         // 409600 float4-units of work

#define NSM_      148
#define CTAS_SM_  4
#define GRID_     (NSM_ * CTAS_SM_)   // 592 CTAs = exactly one wave
#define TPB_      256

// Persistent grid-stride kernel: each thread processes float4 units (4
// consecutive pixels along W). Pure streaming for both inputs; top-2
// (cost, disparity) carried in registers — no gather.
__global__ __launch_bounds__(TPB_, CTAS_SM_) void sparse_regression_kernel(
    const float* __restrict__ cost,
    const float* __restrict__ disp,
    float* __restrict__ out)
{
    const int stride = GRID_ * TPB_;          // 151552 threads
    for (int u = blockIdx.x * TPB_ + threadIdx.x; u < NU_; u += stride) {
        const int p  = u * 4;                 // first pixel of this group
        const int b  = p / HW_;               // HW_ % 4 == 0 -> no b crossing
        const int hw = p - b * HW_;
        const size_t base = (size_t)b * (C_ * HW_) + hw;   // &cost[b][0][hw]

        // Running top-2 (value + disparity) per lane (4 pixels)
        float v1[4], v2[4], d1[4], d2[4];

        // c = 0 initializes
        {
            const float4 cv = __ldcs((const float4*)(cost + base));
            const float4 dv = __ldcs((const float4*)(disp + base));
            const float cc[4] = {cv.x, cv.y, cv.z, cv.w};
            const float dd[4] = {dv.x, dv.y, dv.z, dv.w};
#pragma unroll
            for (int j = 0; j < 4; ++j) {
                v1[j] = cc[j];          d1[j] = dd[j];
                v2[j] = -CUDART_INF_F;  d2[j] = 0.0f;
            }
        }

#pragma unroll
        for (int c = 1; c < C_; ++c) {
            const float4 cv = __ldcs((const float4*)(cost + base + (size_t)c * HW_));
            const float4 dv = __ldcs((const float4*)(disp + base + (size_t)c * HW_));
            const float cc[4] = {cv.x, cv.y, cv.z, cv.w};
            const float dd[4] = {dv.x, dv.y, dv.z, dv.w};
#pragma unroll
            for (int j = 0; j < 4; ++j) {
                const float v  = cc[j];
                const float dI = dd[j];
                const bool gt1 = v > v1[j];
                const bool gt2 = v > v2[j];
                v2[j] = gt1 ? v1[j] : (gt2 ? v  : v2[j]);
                d2[j] = gt1 ? d1[j] : (gt2 ? dI : d2[j]);
                v1[j] = gt1 ? v  : v1[j];
                d1[j] = gt1 ? dI : d1[j];
            }
        }

        // Softmax over the two top costs + weighted sum
        float pj1[4], pj2[4], pd[4];
#pragma unroll
        for (int j = 0; j < 4; ++j) {
            const float e   = __expf(v2[j] - v1[j]);   // <= 1, no overflow
            const float inv = 1.0f / (1.0f + e);
            pj1[j] = inv;
            pj2[j] = e * inv;
            pd[j]  = d1[j] * pj1[j] + d2[j] * pj2[j];
        }

        // Output layout: pred [B,H,W] (NPIX floats) then prob [B,2,H,W]
        __stcs((float4*)(out + p), make_float4(pd[0], pd[1], pd[2], pd[3]));
        float* prob = out + NPIX;
        const size_t pb = (size_t)b * (2 * HW_) + hw;
        __stcs((float4*)(prob + pb),
               make_float4(pj1[0], pj1[1], pj1[2], pj1[3]));   // k = 0
        __stcs((float4*)(prob + pb + HW_),
               make_float4(pj2[0], pj2[1], pj2[2], pj2[3]));   // k = 1
    }
}

extern "C" void kernel_launch(void* const* d_in, const int* in_sizes, int n_in,
                              void* d_out, int out_size)
{
    const float* cost = (const float*)d_in[0];
    const float* disp = (const float*)d_in[1];
    float* out = (float*)d_out;

    sparse_regression_kernel<<<GRID_, TPB_>>>(cost, disp, out);
}

// round 14
// speedup vs baseline: 1.0096x; 1.0096x over previous
#include <cuda_runtime.h>
#include <math_constants.h>

// Problem constants (fixed by reference setup_inputs)
#define B_   8
#define C_   24
#define H_   320
#define W_   640
#define HW_  (H_ * W_)          // 204800
#define NPIX (B_ * HW_)         // 1638400
#define NU_  (NPIX / 4)         // 409600 float4-units of work

#define NSM_      148
#define CTAS_SM_  4
#define GRID_     (NSM_ * CTAS_SM_)   // 592 CTAs = exactly one wave
#define TPB_      256

// Persistent grid-stride kernel: each thread processes float4 units (4
// consecutive pixels along W). Pure streaming for both inputs; top-2
// (cost, disparity) carried in registers — no gather.
__global__ __launch_bounds__(TPB_, CTAS_SM_) void sparse_regression_kernel(
    const float* __restrict__ cost,
    const float* __restrict__ disp,
    float* __restrict__ out)
{
    const int stride = GRID_ * TPB_;          // 151552 threads
    for (int u = blockIdx.x * TPB_ + threadIdx.x; u < NU_; u += stride) {
        const int p  = u * 4;                 // first pixel of this group
        const int b  = p / HW_;               // HW_ % 4 == 0 -> no b crossing
        const int hw = p - b * HW_;
        const size_t base = (size_t)b * (C_ * HW_) + hw;   // &cost[b][0][hw]

        // Running top-2 (value + disparity) per lane (4 pixels)
        float v1[4], v2[4], d1[4], d2[4];

        // c = 0 initializes
        {
            const float4 cv = __ldcs((const float4*)(cost + base));
            const float4 dv = __ldcs((const float4*)(disp + base));
            const float cc[4] = {cv.x, cv.y, cv.z, cv.w};
            const float dd[4] = {dv.x, dv.y, dv.z, dv.w};
#pragma unroll
            for (int j = 0; j < 4; ++j) {
                v1[j] = cc[j];          d1[j] = dd[j];
                v2[j] = -CUDART_INF_F;  d2[j] = 0.0f;
            }
        }

#pragma unroll
        for (int c = 1; c < C_; ++c) {
            const float4 cv = __ldcs((const float4*)(cost + base + (size_t)c * HW_));
            const float4 dv = __ldcs((const float4*)(disp + base + (size_t)c * HW_));
            const float cc[4] = {cv.x, cv.y, cv.z, cv.w};
            const float dd[4] = {dv.x, dv.y, dv.z, dv.w};
#pragma unroll
            for (int j = 0; j < 4; ++j) {
                const float v  = cc[j];
                const float dI = dd[j];
                const bool gt1 = v > v1[j];
                const bool gt2 = v > v2[j];
                v2[j] = gt1 ? v1[j] : (gt2 ? v  : v2[j]);
                d2[j] = gt1 ? d1[j] : (gt2 ? dI : d2[j]);
                v1[j] = gt1 ? v  : v1[j];
                d1[j] = gt1 ? dI : d1[j];
            }
        }

        // Softmax over the two top costs + weighted sum
        float pj1[4], pj2[4], pd[4];
#pragma unroll
        for (int j = 0; j < 4; ++j) {
            const float e   = __expf(v2[j] - v1[j]);   // <= 1, no overflow
            const float inv = 1.0f / (1.0f + e);
            pj1[j] = inv;
            pj2[j] = e * inv;
            pd[j]  = d1[j] * pj1[j] + d2[j] * pj2[j];
        }

        // Output layout: pred [B,H,W] (NPIX floats) then prob [B,2,H,W]
        __stcs((float4*)(out + p), make_float4(pd[0], pd[1], pd[2], pd[3]));
        float* prob = out + NPIX;
        const size_t pb = (size_t)b * (2 * HW_) + hw;
        __stcs((float4*)(prob + pb),
               make_float4(pj1[0], pj1[1], pj1[2], pj1[3]));   // k = 0
        __stcs((float4*)(prob + pb + HW_),
               make_float4(pj2[0], pj2[1], pj2[2], pj2[3]));   // k = 1
    }
}

extern "C" void kernel_launch(void* const* d_in, const int* in_sizes, int n_in,
                              void* d_out, int out_size)
{
    const float* cost = (const float*)d_in[0];
    const float* disp = (const float*)d_in[1];
    float* out = (float*)d_out;

    sparse_regression_kernel<<<GRID_, TPB_>>>(cost, disp, out);
}